// round 5
// baseline (speedup 1.0000x reference)
#include <cuda_runtime.h>
#include <cuda_bf16.h>
#include <math.h>
#include <stdint.h>

#define KTOK   77
#define BATCH  256
#define DMODEL 768
#define NPATCH 576

// ---- fused kernel geometry ----
#define BM    96                  // M tile (77 padded)
#define BN    192                 // N tile per pass (3 passes = 576)
#define KC    32                  // K chunk (bf16)
#define NCH   (DMODEL / KC)       // 24
#define STRW  20                  // staging row stride in words (conflict-free frags)
#define SROWW 292                 // S row stride in words (584 bf16): 4*l4+lm banks
#define CCAP  64                  // per-warp candidate cap

// dynamic smem offsets (bytes)
#define OFF_S   0
#define SZ_S    (KTOK * SROWW * 4)            // 89,936
#define OFF_A   (OFF_S + SZ_S)
#define SZ_A    (BM * STRW * 4)               // 7,680
#define OFF_B   (OFF_A + SZ_A)
#define SZ_B    (BN * STRW * 4)               // 15,360
#define OFF_CI  (OFF_B + SZ_B)
#define SZ_CI   (8 * CCAP * 2)                // 1,024
#define OFF_CS  (OFF_CI + SZ_CI)
#define SZ_CS   (8 * CCAP * 4)                // 2,048
#define SMEM_TOTAL (OFF_CS + SZ_CS)           // 116,048

#define CWIN 4.0f

__device__ __forceinline__ void mma_bf16(float* c, const uint32_t* a, const uint32_t* b) {
    asm volatile(
        "mma.sync.aligned.m16n8k16.row.col.f32.bf16.bf16.f32 "
        "{%0,%1,%2,%3}, {%4,%5,%6,%7}, {%8,%9}, {%0,%1,%2,%3};"
        : "+f"(c[0]), "+f"(c[1]), "+f"(c[2]), "+f"(c[3])
        : "r"(a[0]), "r"(a[1]), "r"(a[2]), "r"(a[3]), "r"(b[0]), "r"(b[1]));
}
__device__ __forceinline__ uint32_t pack_bf2(float x, float y) {
    __nv_bfloat162 h = __floats2bfloat162_rn(x, y);
    return *(uint32_t*)&h;
}

__global__ __launch_bounds__(256, 2)
void fused_kernel(const float* __restrict__ text,
                  const float* __restrict__ vision,
                  float* __restrict__ out) {
    extern __shared__ __align__(16) char dsm[];
    uint32_t* Ssm = (uint32_t*)(dsm + OFF_S);           // bf16 scores, word-addressed
    uint32_t* As  = (uint32_t*)(dsm + OFF_A);
    uint32_t* Bs  = (uint32_t*)(dsm + OFF_B);
    unsigned short* cidx = (unsigned short*)(dsm + OFF_CI);
    float* csv = (float*)(dsm + OFF_CS);
    __shared__ int cnt[8];

    const int tid  = threadIdx.x;
    const int wid  = tid >> 5;
    const int lane = tid & 31;
    const int b    = blockIdx.x;

    const int l4 = lane >> 2;
    const int lm = lane & 3;
    const int mb = (wid >> 2) * 48;          // warp M offset (0,48)
    const int nb = (wid & 3) * 48;           // warp N offset (0,48,96,144)

    // ================= Phase 1: scores into SMEM (bf16) =================
    for (int nt = 0; nt < 3; ++nt) {
        const int n0 = nt * BN;

        float acc[3][6][4];
#pragma unroll
        for (int i = 0; i < 3; ++i)
#pragma unroll
            for (int j = 0; j < 6; ++j)
#pragma unroll
                for (int q = 0; q < 4; ++q) acc[i][j][q] = 0.f;

        for (int c = 0; c < NCH; ++c) {
            const int d0 = c * KC;

            float4 rg[9];
#pragma unroll
            for (int it = 0; it < 9; ++it) {
                int q = tid + it * 256;
                if (q < 768) {                       // A: 96 rows x 8 float4
                    int r = q >> 3, f4 = q & 7;
                    int rr = r < KTOK ? r : KTOK - 1;
                    rg[it] = *(const float4*)&text[((size_t)rr * BATCH + b) * DMODEL + d0 + f4 * 4];
                } else {                             // B: 192 rows x 8 float4
                    int q2 = q - 768;
                    int r = q2 >> 3, f4 = q2 & 7;
                    rg[it] = *(const float4*)&vision[((size_t)(n0 + r) * BATCH + b) * DMODEL + d0 + f4 * 4];
                }
            }
            __syncthreads();         // prev chunk's MMA done reading staging

#pragma unroll
            for (int it = 0; it < 9; ++it) {
                int q = tid + it * 256;
                uint32_t w0 = pack_bf2(rg[it].x, rg[it].y);
                uint32_t w1 = pack_bf2(rg[it].z, rg[it].w);
                if (q < 768) {
                    int r = q >> 3, f4 = q & 7;
                    uint32_t* p = As + r * STRW + f4 * 2;
                    p[0] = w0; p[1] = w1;
                } else {
                    int q2 = q - 768;
                    int r = q2 >> 3, f4 = q2 & 7;
                    uint32_t* p = Bs + r * STRW + f4 * 2;
                    p[0] = w0; p[1] = w1;
                }
            }
            __syncthreads();

#pragma unroll
            for (int ks = 0; ks < 2; ++ks) {
                const int kw = ks * 8;
                uint32_t af[3][4], bf[6][2];
#pragma unroll
                for (int mf = 0; mf < 3; ++mf) {
                    const uint32_t* p = As + (mb + mf * 16 + l4) * STRW + kw + lm;
                    af[mf][0] = p[0];
                    af[mf][1] = p[8 * STRW];
                    af[mf][2] = p[4];
                    af[mf][3] = p[8 * STRW + 4];
                }
#pragma unroll
                for (int nf = 0; nf < 6; ++nf) {
                    const uint32_t* p = Bs + (nb + nf * 8 + l4) * STRW + kw + lm;
                    bf[nf][0] = p[0];
                    bf[nf][1] = p[4];
                }
#pragma unroll
                for (int mf = 0; mf < 3; ++mf)
#pragma unroll
                    for (int nf = 0; nf < 6; ++nf)
                        mma_bf16(acc[mf][nf], af[mf], bf[nf]);
            }
        }

        // epilogue: acc -> bf16 S in smem. (c0,c1)@(m0,n), (c2,c3)@(m0+8,n)
#pragma unroll
        for (int mf = 0; mf < 3; ++mf) {
            const int m0 = mb + mf * 16 + l4;
#pragma unroll
            for (int nf = 0; nf < 6; ++nf) {
                const int col = n0 + nb + nf * 8 + 2 * lm;   // even
                if (m0 < KTOK)
                    Ssm[m0 * SROWW + (col >> 1)] = pack_bf2(acc[mf][nf][0], acc[mf][nf][1]);
                if (m0 + 8 < KTOK)
                    Ssm[(m0 + 8) * SROWW + (col >> 1)] = pack_bf2(acc[mf][nf][2], acc[mf][nf][3]);
            }
        }
        __syncthreads();   // S tile written before staging reuse next nt
    }

    // ================= Phase 2: sparse softmax + decode =================
    // rows striped over the 8 warps; S scanned from SMEM
    for (int k = wid; k < KTOK; k += 8) {
        const uint32_t* srow = Ssm + k * SROWW;

        // pass 1: row max over 576 bf16 (9 words/lane)
        float m = -INFINITY;
        float2 vals[9];
#pragma unroll
        for (int i = 0; i < 9; ++i) {
            uint32_t w = srow[lane + 32 * i];
            vals[i] = __bfloat1622float2(*(__nv_bfloat162*)&w);
            m = fmaxf(m, fmaxf(vals[i].x, vals[i].y));
        }
#pragma unroll
        for (int o = 16; o; o >>= 1) m = fmaxf(m, __shfl_xor_sync(~0u, m, o));

        // pass 2: collect candidates
        if (lane == 0) cnt[wid] = 0;
        __syncwarp();
        const float th = m - CWIN;
#pragma unroll
        for (int i = 0; i < 9; ++i) {
            int n2 = (lane + 32 * i) << 1;
            if (vals[i].x >= th) {
                int p = atomicAdd(&cnt[wid], 1);
                if (p < CCAP) cidx[wid * CCAP + p] = (unsigned short)n2;
            }
            if (vals[i].y >= th) {
                int p = atomicAdd(&cnt[wid], 1);
                if (p < CCAP) cidx[wid * CCAP + p] = (unsigned short)(n2 + 1);
            }
        }
        __syncwarp();
        int c = cnt[wid];
        if (c > CCAP) c = CCAP;

        // exact fp32 dot per candidate
        const float* trow = text + ((size_t)k * BATCH + b) * DMODEL;
        for (int ci = 0; ci < c; ++ci) {
            const float* vrow = vision + ((size_t)cidx[wid * CCAP + ci] * BATCH + b) * DMODEL;
            float s = 0.f;
#pragma unroll
            for (int i = 0; i < 6; ++i) {
                int d = (lane + 32 * i) << 2;
                float4 t4 = *(const float4*)&trow[d];
                float4 v4 = *(const float4*)&vrow[d];
                s = fmaf(t4.x, v4.x, s);
                s = fmaf(t4.y, v4.y, s);
                s = fmaf(t4.z, v4.z, s);
                s = fmaf(t4.w, v4.w, s);
            }
#pragma unroll
            for (int o = 16; o; o >>= 1) s += __shfl_xor_sync(~0u, s, o);
            if (lane == 0) csv[wid * CCAP + ci] = s;
            __syncwarp();
        }

        // softmax over candidates (exact scores)
        float mx = -INFINITY;
        for (int ci = 0; ci < c; ++ci) mx = fmaxf(mx, csv[wid * CCAP + ci]);
        float denom = 0.f;
        for (int ci = 0; ci < c; ++ci) denom += expf((csv[wid * CCAP + ci] - mx) / 0.07f);
        const float inv = 1.f / denom;
        for (int ci = lane; ci < c; ci += 32)
            csv[wid * CCAP + ci] = expf((csv[wid * CCAP + ci] - mx) / 0.07f) * inv;
        __syncwarp();

        // decoded row = sum_c w_c * vision[n_c, b, :]
        float4 o4[6];
#pragma unroll
        for (int i = 0; i < 6; ++i) o4[i] = make_float4(0.f, 0.f, 0.f, 0.f);

        for (int ci = 0; ci < c; ++ci) {
            float w = csv[wid * CCAP + ci];
            if (w < 1e-12f) continue;
            const float* vrow = vision + ((size_t)cidx[wid * CCAP + ci] * BATCH + b) * DMODEL;
#pragma unroll
            for (int i = 0; i < 6; ++i) {
                int d = (lane + 32 * i) << 2;
                float4 v4 = *(const float4*)&vrow[d];
                o4[i].x = fmaf(w, v4.x, o4[i].x);
                o4[i].y = fmaf(w, v4.y, o4[i].y);
                o4[i].z = fmaf(w, v4.z, o4[i].z);
                o4[i].w = fmaf(w, v4.w, o4[i].w);
            }
        }

        float* orow = out + ((size_t)k * BATCH + b) * DMODEL;
#pragma unroll
        for (int i = 0; i < 6; ++i)
            *(float4*)&orow[(lane + 32 * i) << 2] = o4[i];
    }
}

// ---------------- launch ----------------
extern "C" void kernel_launch(void* const* d_in, const int* in_sizes, int n_in,
                              void* d_out, int out_size) {
    const float* text   = (const float*)d_in[0];
    const float* vision = (const float*)d_in[1];
    float* out          = (float*)d_out;

    cudaFuncSetAttribute(fused_kernel,
                         cudaFuncAttributeMaxDynamicSharedMemorySize, SMEM_TOTAL);
    fused_kernel<<<BATCH, 256, SMEM_TOTAL>>>(text, vision, out);
}

// round 6
// speedup vs baseline: 1.2918x; 1.2918x over previous
#include <cuda_runtime.h>
#include <cuda_bf16.h>
#include <math.h>
#include <stdint.h>

#define KTOK   77
#define BATCH  256
#define DMODEL 768
#define NPATCH 576
#define NROWS  (KTOK * BATCH)      // 19712

// ---- candidate lists (replace the 45 MB S matrix) ----
#define CAP 96
__device__ int   g_cnt[NROWS];
__device__ int   g_cidx[(size_t)NROWS * CAP];
__device__ float g_cval[(size_t)NROWS * CAP];

// windows: collection (tile-local) must be >= decode filter window
#define CWIN_COLLECT 4.0f
#define CWIN_FILTER  3.5f

// ---------------- GEMM geometry (R4-proven) ----------------
#define BM    96
#define BN    192
#define KC    32
#define NCH   (DMODEL / KC)      // 24
#define STRW  20                 // staging row stride (words)
#define AWRD  (BM * STRW)        // 1920
#define BWRD  (BN * STRW)        // 3840
#define SSTR  100                // S tile row stride (words, 200 bf16): 4*l4+lm banks
#define SWRD  (BM * SSTR)        // 9600
#define DYN_SMEM ((AWRD + BWRD + SWRD) * 4)   // 61,440 B

__device__ __forceinline__ void mma_bf16(float* c, const uint32_t* a, const uint32_t* b) {
    asm volatile(
        "mma.sync.aligned.m16n8k16.row.col.f32.bf16.bf16.f32 "
        "{%0,%1,%2,%3}, {%4,%5,%6,%7}, {%8,%9}, {%0,%1,%2,%3};"
        : "+f"(c[0]), "+f"(c[1]), "+f"(c[2]), "+f"(c[3])
        : "r"(a[0]), "r"(a[1]), "r"(a[2]), "r"(a[3]), "r"(b[0]), "r"(b[1]));
}
__device__ __forceinline__ uint32_t pack_bf2(float x, float y) {
    __nv_bfloat162 h = __floats2bfloat162_rn(x, y);
    return *(uint32_t*)&h;
}

__global__ void zero_cnt_kernel() {
    int i = blockIdx.x * blockDim.x + threadIdx.x;
    if (i < NROWS) g_cnt[i] = 0;
}

// ---------------- Kernel A: scores + candidate extraction ----------------
__global__ __launch_bounds__(256, 2)
void scores_mma_kernel(const float* __restrict__ text,
                       const float* __restrict__ vision) {
    extern __shared__ __align__(16) uint32_t sm[];
    uint32_t* As  = sm;
    uint32_t* Bs  = sm + AWRD;
    uint32_t* Ssm = sm + AWRD + BWRD;       // bf16 S tile, 96 x 192

    const int tid  = threadIdx.x;
    const int wid  = tid >> 5;
    const int lane = tid & 31;
    const int b    = blockIdx.y;
    const int n0   = blockIdx.x * BN;

    const int l4 = lane >> 2;
    const int lm = lane & 3;
    const int mb = (wid >> 2) * 48;
    const int nb = (wid & 3) * 48;

    float acc[3][6][4];
#pragma unroll
    for (int i = 0; i < 3; ++i)
#pragma unroll
        for (int j = 0; j < 6; ++j)
#pragma unroll
            for (int q = 0; q < 4; ++q) acc[i][j][q] = 0.f;

    for (int c = 0; c < NCH; ++c) {
        const int d0 = c * KC;

        float4 rg[9];
#pragma unroll
        for (int it = 0; it < 9; ++it) {
            int q = tid + it * 256;
            if (q < 768) {
                int r = q >> 3, f4 = q & 7;
                int rr = r < KTOK ? r : KTOK - 1;
                rg[it] = *(const float4*)&text[((size_t)rr * BATCH + b) * DMODEL + d0 + f4 * 4];
            } else {
                int q2 = q - 768;
                int r = q2 >> 3, f4 = q2 & 7;
                rg[it] = *(const float4*)&vision[((size_t)(n0 + r) * BATCH + b) * DMODEL + d0 + f4 * 4];
            }
        }
        __syncthreads();

#pragma unroll
        for (int it = 0; it < 9; ++it) {
            int q = tid + it * 256;
            uint32_t w0 = pack_bf2(rg[it].x, rg[it].y);
            uint32_t w1 = pack_bf2(rg[it].z, rg[it].w);
            if (q < 768) {
                int r = q >> 3, f4 = q & 7;
                uint32_t* p = As + r * STRW + f4 * 2;
                p[0] = w0; p[1] = w1;
            } else {
                int q2 = q - 768;
                int r = q2 >> 3, f4 = q2 & 7;
                uint32_t* p = Bs + r * STRW + f4 * 2;
                p[0] = w0; p[1] = w1;
            }
        }
        __syncthreads();

#pragma unroll
        for (int ks = 0; ks < 2; ++ks) {
            const int kw = ks * 8;
            uint32_t af[3][4], bf[6][2];
#pragma unroll
            for (int mf = 0; mf < 3; ++mf) {
                const uint32_t* p = As + (mb + mf * 16 + l4) * STRW + kw + lm;
                af[mf][0] = p[0];
                af[mf][1] = p[8 * STRW];
                af[mf][2] = p[4];
                af[mf][3] = p[8 * STRW + 4];
            }
#pragma unroll
            for (int nf = 0; nf < 6; ++nf) {
                const uint32_t* p = Bs + (nb + nf * 8 + l4) * STRW + kw + lm;
                bf[nf][0] = p[0];
                bf[nf][1] = p[4];
            }
#pragma unroll
            for (int mf = 0; mf < 3; ++mf)
#pragma unroll
                for (int nf = 0; nf < 6; ++nf)
                    mma_bf16(acc[mf][nf], af[mf], bf[nf]);
        }
    }
    __syncthreads();   // staging reads done (also orders before S-tile scan below)

    // ---- store acc -> bf16 S tile in smem ----
#pragma unroll
    for (int mf = 0; mf < 3; ++mf) {
        const int m0 = mb + mf * 16 + l4;
#pragma unroll
        for (int nf = 0; nf < 6; ++nf) {
            const int colw = (nb + nf * 8 + 2 * lm) >> 1;
            Ssm[m0 * SSTR + colw]       = pack_bf2(acc[mf][nf][0], acc[mf][nf][1]);
            Ssm[(m0 + 8) * SSTR + colw] = pack_bf2(acc[mf][nf][2], acc[mf][nf][3]);
        }
    }
    __syncthreads();

    // ---- scan rows: tile-local max, push candidates within CWIN_COLLECT ----
    for (int k = wid; k < KTOK; k += 8) {
        float2 v[3];
        float m = -INFINITY;
#pragma unroll
        for (int i = 0; i < 3; ++i) {
            uint32_t w = Ssm[k * SSTR + lane + 32 * i];
            v[i] = __bfloat1622float2(*(__nv_bfloat162*)&w);
            m = fmaxf(m, fmaxf(v[i].x, v[i].y));
        }
#pragma unroll
        for (int o = 16; o; o >>= 1) m = fmaxf(m, __shfl_xor_sync(~0u, m, o));

        const float th = m - CWIN_COLLECT;
        const int row = b * KTOK + k;
#pragma unroll
        for (int i = 0; i < 3; ++i) {
            int n2 = n0 + ((lane + 32 * i) << 1);
            if (v[i].x >= th) {
                int p = atomicAdd(&g_cnt[row], 1);
                if (p < CAP) { g_cidx[(size_t)row * CAP + p] = n2;     g_cval[(size_t)row * CAP + p] = v[i].x; }
            }
            if (v[i].y >= th) {
                int p = atomicAdd(&g_cnt[row], 1);
                if (p < CAP) { g_cidx[(size_t)row * CAP + p] = n2 + 1; g_cval[(size_t)row * CAP + p] = v[i].y; }
            }
        }
    }
}

// ---------------- Kernel B: candidate decode ----------------
__global__ __launch_bounds__(256)
void decode_kernel(const float* __restrict__ text,
                   const float* __restrict__ vision,
                   float* __restrict__ out) {
    __shared__ int   sidx[8][CAP];
    __shared__ float sval[8][CAP];

    const int wid  = threadIdx.x >> 5;
    const int lane = threadIdx.x & 31;
    const int row  = blockIdx.x * 8 + wid;      // = b*77 + k
    if (row >= NROWS) return;
    const int b = row / KTOK;
    const int k = row % KTOK;

    int c = g_cnt[row];
    if (c > CAP) c = CAP;

    for (int ci = lane; ci < c; ci += 32) {
        sidx[wid][ci] = g_cidx[(size_t)row * CAP + ci];
        sval[wid][ci] = g_cval[(size_t)row * CAP + ci];
    }
    __syncwarp();

    // deterministic order: insertion sort by index (set is order-invariant)
    if (lane == 0) {
        for (int i = 1; i < c; ++i) {
            int   ix = sidx[wid][i];
            float vx = sval[wid][i];
            int j = i - 1;
            while (j >= 0 && sidx[wid][j] > ix) {
                sidx[wid][j + 1] = sidx[wid][j];
                sval[wid][j + 1] = sval[wid][j];
                --j;
            }
            sidx[wid][j + 1] = ix;
            sval[wid][j + 1] = vx;
        }
        // filter against global (approx) max, compact in place
        float vmax = -INFINITY;
        for (int i = 0; i < c; ++i) vmax = fmaxf(vmax, sval[wid][i]);
        const float th = vmax - CWIN_FILTER;
        int w = 0;
        for (int i = 0; i < c; ++i)
            if (sval[wid][i] >= th) {
                sidx[wid][w] = sidx[wid][i];
                ++w;
            }
        sval[wid][CAP - 1] = __int_as_float(w);   // stash count (c<CAP slot unused)
    }
    __syncwarp();
    const int c2 = __float_as_int(sval[wid][CAP - 1]);

    // exact fp32 dots
    const float* trow = text + ((size_t)k * BATCH + b) * DMODEL;
    for (int ci = 0; ci < c2; ++ci) {
        const float* vrow = vision + ((size_t)sidx[wid][ci] * BATCH + b) * DMODEL;
        float s = 0.f;
#pragma unroll
        for (int i = 0; i < 6; ++i) {
            int d = (lane + 32 * i) << 2;
            float4 t4 = *(const float4*)&trow[d];
            float4 v4 = *(const float4*)&vrow[d];
            s = fmaf(t4.x, v4.x, s);
            s = fmaf(t4.y, v4.y, s);
            s = fmaf(t4.z, v4.z, s);
            s = fmaf(t4.w, v4.w, s);
        }
#pragma unroll
        for (int o = 16; o; o >>= 1) s += __shfl_xor_sync(~0u, s, o);
        if (lane == 0) sval[wid][ci] = s;
        __syncwarp();
    }

    // softmax over exact scores (serial, deterministic order)
    float mx = -INFINITY;
    for (int ci = 0; ci < c2; ++ci) mx = fmaxf(mx, sval[wid][ci]);
    float denom = 0.f;
    for (int ci = 0; ci < c2; ++ci) denom += expf((sval[wid][ci] - mx) / 0.07f);
    const float inv = 1.f / denom;

    // weighted sum of vision rows
    float4 o4[6];
#pragma unroll
    for (int i = 0; i < 6; ++i) o4[i] = make_float4(0.f, 0.f, 0.f, 0.f);

    for (int ci = 0; ci < c2; ++ci) {
        float w = expf((sval[wid][ci] - mx) / 0.07f) * inv;
        if (w < 1e-12f) continue;
        const float* vrow = vision + ((size_t)sidx[wid][ci] * BATCH + b) * DMODEL;
#pragma unroll
        for (int i = 0; i < 6; ++i) {
            int d = (lane + 32 * i) << 2;
            float4 v4 = *(const float4*)&vrow[d];
            o4[i].x = fmaf(w, v4.x, o4[i].x);
            o4[i].y = fmaf(w, v4.y, o4[i].y);
            o4[i].z = fmaf(w, v4.z, o4[i].z);
            o4[i].w = fmaf(w, v4.w, o4[i].w);
        }
    }

    float* orow = out + ((size_t)k * BATCH + b) * DMODEL;
#pragma unroll
    for (int i = 0; i < 6; ++i)
        *(float4*)&orow[(lane + 32 * i) << 2] = o4[i];
}

// ---------------- launch ----------------
extern "C" void kernel_launch(void* const* d_in, const int* in_sizes, int n_in,
                              void* d_out, int out_size) {
    const float* text   = (const float*)d_in[0];
    const float* vision = (const float*)d_in[1];
    float* out          = (float*)d_out;

    zero_cnt_kernel<<<(NROWS + 1023) / 1024, 1024>>>();

    cudaFuncSetAttribute(scores_mma_kernel,
                         cudaFuncAttributeMaxDynamicSharedMemorySize, DYN_SMEM);
    dim3 g1(NPATCH / BN, BATCH);                 // 3 x 256, x fastest => text L2 reuse
    scores_mma_kernel<<<g1, 256, DYN_SMEM>>>(text, vision);

    decode_kernel<<<(NROWS + 7) / 8, 256>>>(text, vision, out);
}

// round 7
// speedup vs baseline: 1.4348x; 1.1107x over previous
#include <cuda_runtime.h>
#include <cuda_bf16.h>
#include <math.h>
#include <stdint.h>

#define KTOK   77
#define BATCH  256
#define DMODEL 768
#define NPATCH 576
#define NROWS  (KTOK * BATCH)      // 19712

// ---- candidate lists (replace the 45 MB S matrix) ----
#define CAP 96
__device__ int   g_cnt[NROWS];     // zero-initialized at load; decode re-zeroes
__device__ int   g_cidx[(size_t)NROWS * CAP];
__device__ float g_cval[(size_t)NROWS * CAP];

// windows: collection (tile-local) must be >= decode filter window
#define CWIN_COLLECT 4.0f
#define CWIN_FILTER  3.5f

// ---------------- GEMM geometry ----------------
#define BM    96
#define BN    192
#define KC    32
#define NCH   (DMODEL / KC)      // 24
#define STRW  20                 // staging row stride (words)
#define AWRD  (BM * STRW)        // 1920
#define BWRD  (BN * STRW)        // 3840
#define BUFW  (AWRD + BWRD)      // 5760 words per stage
#define SSTR  100                // S tile row stride (words)
#define SWRD  (BM * SSTR)        // 9600
#define DYN_SMEM ((2 * BUFW + SWRD) * 4)   // 84,480 B

__device__ __forceinline__ void mma_bf16(float* c, const uint32_t* a, const uint32_t* b) {
    asm volatile(
        "mma.sync.aligned.m16n8k16.row.col.f32.bf16.bf16.f32 "
        "{%0,%1,%2,%3}, {%4,%5,%6,%7}, {%8,%9}, {%0,%1,%2,%3};"
        : "+f"(c[0]), "+f"(c[1]), "+f"(c[2]), "+f"(c[3])
        : "r"(a[0]), "r"(a[1]), "r"(a[2]), "r"(a[3]), "r"(b[0]), "r"(b[1]));
}
__device__ __forceinline__ uint32_t pack_bf2(float x, float y) {
    __nv_bfloat162 h = __floats2bfloat162_rn(x, y);
    return *(uint32_t*)&h;
}

// load 16 floats worth? no: each slot loads one float4 -> packed uint2
__device__ __forceinline__ void ldg_chunk(const float* __restrict__ text,
                                          const float* __restrict__ vision,
                                          int b, int n0, int d0, int tid, uint2 rg[9]) {
#pragma unroll
    for (int it = 0; it < 9; ++it) {
        int q = tid + it * 256;
        float4 f;
        if (q < 768) {                       // A: 96 rows x 8 float4
            int r = q >> 3, f4 = q & 7;
            int rr = r < KTOK ? r : KTOK - 1;
            f = *(const float4*)&text[((size_t)rr * BATCH + b) * DMODEL + d0 + f4 * 4];
        } else {                             // B: 192 rows x 8 float4
            int q2 = q - 768;
            int r = q2 >> 3, f4 = q2 & 7;
            f = *(const float4*)&vision[((size_t)(n0 + r) * BATCH + b) * DMODEL + d0 + f4 * 4];
        }
        rg[it].x = pack_bf2(f.x, f.y);
        rg[it].y = pack_bf2(f.z, f.w);
    }
}

__device__ __forceinline__ void sts_chunk(uint32_t* As, uint32_t* Bs, int tid,
                                          const uint2 rg[9]) {
#pragma unroll
    for (int it = 0; it < 9; ++it) {
        int q = tid + it * 256;
        if (q < 768) {
            int r = q >> 3, f4 = q & 7;
            *(uint2*)(As + r * STRW + f4 * 2) = rg[it];
        } else {
            int q2 = q - 768;
            int r = q2 >> 3, f4 = q2 & 7;
            *(uint2*)(Bs + r * STRW + f4 * 2) = rg[it];
        }
    }
}

// ---------------- Kernel A: scores + candidate extraction ----------------
__global__ __launch_bounds__(256, 2)
void scores_mma_kernel(const float* __restrict__ text,
                       const float* __restrict__ vision) {
    extern __shared__ __align__(16) uint32_t sm[];
    uint32_t* Ssm = sm + 2 * BUFW;          // bf16 S tile, 96 x 192

    const int tid  = threadIdx.x;
    const int wid  = tid >> 5;
    const int lane = tid & 31;
    const int b    = blockIdx.y;
    const int n0   = blockIdx.x * BN;

    const int l4 = lane >> 2;
    const int lm = lane & 3;
    const int mb = (wid >> 2) * 48;
    const int nb = (wid & 3) * 48;

    float acc[3][6][4];
#pragma unroll
    for (int i = 0; i < 3; ++i)
#pragma unroll
        for (int j = 0; j < 6; ++j)
#pragma unroll
            for (int q = 0; q < 4; ++q) acc[i][j][q] = 0.f;

    uint2 rg[9];
    ldg_chunk(text, vision, b, n0, 0, tid, rg);
    sts_chunk(sm, sm + AWRD, tid, rg);
    __syncthreads();

    for (int c = 0; c < NCH; ++c) {
        // prefetch next chunk (LDG latency covered by this chunk's MMAs)
        if (c + 1 < NCH)
            ldg_chunk(text, vision, b, n0, (c + 1) * KC, tid, rg);

        const uint32_t* As = sm + (c & 1) * BUFW;
        const uint32_t* Bs = As + AWRD;

#pragma unroll
        for (int ks = 0; ks < 2; ++ks) {
            const int kw = ks * 8;
            uint32_t af[3][4], bf[6][2];
#pragma unroll
            for (int mf = 0; mf < 3; ++mf) {
                const uint32_t* p = As + (mb + mf * 16 + l4) * STRW + kw + lm;
                af[mf][0] = p[0];
                af[mf][1] = p[8 * STRW];
                af[mf][2] = p[4];
                af[mf][3] = p[8 * STRW + 4];
            }
#pragma unroll
            for (int nf = 0; nf < 6; ++nf) {
                const uint32_t* p = Bs + (nb + nf * 8 + l4) * STRW + kw + lm;
                bf[nf][0] = p[0];
                bf[nf][1] = p[4];
            }
#pragma unroll
            for (int mf = 0; mf < 3; ++mf)
#pragma unroll
                for (int nf = 0; nf < 6; ++nf)
                    mma_bf16(acc[mf][nf], af[mf], bf[nf]);
        }

        // store prefetched data into the other buffer (its old readers finished
        // before the previous iteration's barrier)
        if (c + 1 < NCH) {
            uint32_t* nAs = sm + ((c + 1) & 1) * BUFW;
            sts_chunk(nAs, nAs + AWRD, tid, rg);
        }
        __syncthreads();
    }

    // ---- store acc -> bf16 S tile in smem ----
#pragma unroll
    for (int mf = 0; mf < 3; ++mf) {
        const int m0 = mb + mf * 16 + l4;
#pragma unroll
        for (int nf = 0; nf < 6; ++nf) {
            const int colw = (nb + nf * 8 + 2 * lm) >> 1;
            Ssm[m0 * SSTR + colw]       = pack_bf2(acc[mf][nf][0], acc[mf][nf][1]);
            Ssm[(m0 + 8) * SSTR + colw] = pack_bf2(acc[mf][nf][2], acc[mf][nf][3]);
        }
    }
    __syncthreads();

    // ---- scan rows: tile-local max, push candidates within CWIN_COLLECT ----
    for (int k = wid; k < KTOK; k += 8) {
        float2 v[3];
        float m = -INFINITY;
#pragma unroll
        for (int i = 0; i < 3; ++i) {
            uint32_t w = Ssm[k * SSTR + lane + 32 * i];
            v[i] = __bfloat1622float2(*(__nv_bfloat162*)&w);
            m = fmaxf(m, fmaxf(v[i].x, v[i].y));
        }
#pragma unroll
        for (int o = 16; o; o >>= 1) m = fmaxf(m, __shfl_xor_sync(~0u, m, o));

        const float th = m - CWIN_COLLECT;
        const int row = b * KTOK + k;
#pragma unroll
        for (int i = 0; i < 3; ++i) {
            int n2 = n0 + ((lane + 32 * i) << 1);
            if (v[i].x >= th) {
                int p = atomicAdd(&g_cnt[row], 1);
                if (p < CAP) { g_cidx[(size_t)row * CAP + p] = n2;     g_cval[(size_t)row * CAP + p] = v[i].x; }
            }
            if (v[i].y >= th) {
                int p = atomicAdd(&g_cnt[row], 1);
                if (p < CAP) { g_cidx[(size_t)row * CAP + p] = n2 + 1; g_cval[(size_t)row * CAP + p] = v[i].y; }
            }
        }
    }
}

// ---------------- Kernel B: candidate decode ----------------
__global__ __launch_bounds__(256)
void decode_kernel(const float* __restrict__ text,
                   const float* __restrict__ vision,
                   float* __restrict__ out) {
    __shared__ int   sidx[8][CAP];
    __shared__ float sval[8][CAP];

    const int wid  = threadIdx.x >> 5;
    const int lane = threadIdx.x & 31;
    const int row  = blockIdx.x * 8 + wid;      // = b*77 + k
    if (row >= NROWS) return;
    const int b = row / KTOK;
    const int k = row % KTOK;

    int c = g_cnt[row];
    if (c > CAP) c = CAP;

    for (int ci = lane; ci < c; ci += 32) {
        sidx[wid][ci] = g_cidx[(size_t)row * CAP + ci];
        sval[wid][ci] = g_cval[(size_t)row * CAP + ci];
    }
    if (lane == 0) g_cnt[row] = 0;     // reset for the next graph replay
    __syncwarp();

    // deterministic order: insertion sort by index (set is order-invariant)
    if (lane == 0) {
        for (int i = 1; i < c; ++i) {
            int   ix = sidx[wid][i];
            float vx = sval[wid][i];
            int j = i - 1;
            while (j >= 0 && sidx[wid][j] > ix) {
                sidx[wid][j + 1] = sidx[wid][j];
                sval[wid][j + 1] = sval[wid][j];
                --j;
            }
            sidx[wid][j + 1] = ix;
            sval[wid][j + 1] = vx;
        }
        // filter against global (approx) max, compact in place
        float vmax = -INFINITY;
        for (int i = 0; i < c; ++i) vmax = fmaxf(vmax, sval[wid][i]);
        const float th = vmax - CWIN_FILTER;
        int w = 0;
        for (int i = 0; i < c; ++i)
            if (sval[wid][i] >= th) {
                sidx[wid][w] = sidx[wid][i];
                ++w;
            }
        sval[wid][CAP - 1] = __int_as_float(w);
    }
    __syncwarp();
    const int c2 = __float_as_int(sval[wid][CAP - 1]);

    // exact fp32 dots
    const float* trow = text + ((size_t)k * BATCH + b) * DMODEL;
    for (int ci = 0; ci < c2; ++ci) {
        const float* vrow = vision + ((size_t)sidx[wid][ci] * BATCH + b) * DMODEL;
        float s = 0.f;
#pragma unroll
        for (int i = 0; i < 6; ++i) {
            int d = (lane + 32 * i) << 2;
            float4 t4 = *(const float4*)&trow[d];
            float4 v4 = *(const float4*)&vrow[d];
            s = fmaf(t4.x, v4.x, s);
            s = fmaf(t4.y, v4.y, s);
            s = fmaf(t4.z, v4.z, s);
            s = fmaf(t4.w, v4.w, s);
        }
#pragma unroll
        for (int o = 16; o; o >>= 1) s += __shfl_xor_sync(~0u, s, o);
        if (lane == 0) sval[wid][ci] = s;
        __syncwarp();
    }

    // softmax over exact scores
    float mx = -INFINITY;
    for (int ci = 0; ci < c2; ++ci) mx = fmaxf(mx, sval[wid][ci]);
    float denom = 0.f;
    for (int ci = 0; ci < c2; ++ci) denom += expf((sval[wid][ci] - mx) / 0.07f);
    const float inv = 1.f / denom;

    // weighted sum of vision rows
    float4 o4[6];
#pragma unroll
    for (int i = 0; i < 6; ++i) o4[i] = make_float4(0.f, 0.f, 0.f, 0.f);

    for (int ci = 0; ci < c2; ++ci) {
        float w = expf((sval[wid][ci] - mx) / 0.07f) * inv;
        if (w < 1e-12f) continue;
        const float* vrow = vision + ((size_t)sidx[wid][ci] * BATCH + b) * DMODEL;
#pragma unroll
        for (int i = 0; i < 6; ++i) {
            int d = (lane + 32 * i) << 2;
            float4 v4 = *(const float4*)&vrow[d];
            o4[i].x = fmaf(w, v4.x, o4[i].x);
            o4[i].y = fmaf(w, v4.y, o4[i].y);
            o4[i].z = fmaf(w, v4.z, o4[i].z);
            o4[i].w = fmaf(w, v4.w, o4[i].w);
        }
    }

    float* orow = out + ((size_t)k * BATCH + b) * DMODEL;
#pragma unroll
    for (int i = 0; i < 6; ++i)
        *(float4*)&orow[(lane + 32 * i) << 2] = o4[i];
}

// ---------------- launch ----------------
extern "C" void kernel_launch(void* const* d_in, const int* in_sizes, int n_in,
                              void* d_out, int out_size) {
    const float* text   = (const float*)d_in[0];
    const float* vision = (const float*)d_in[1];
    float* out          = (float*)d_out;

    cudaFuncSetAttribute(scores_mma_kernel,
                         cudaFuncAttributeMaxDynamicSharedMemorySize, DYN_SMEM);
    dim3 g1(NPATCH / BN, BATCH);                 // 3 x 256, x fastest => text L2 reuse
    scores_mma_kernel<<<g1, 256, DYN_SMEM>>>(text, vision);

    decode_kernel<<<(NROWS + 7) / 8, 256>>>(text, vision, out);
}